// round 1
// baseline (speedup 1.0000x reference)
#include <cuda_runtime.h>

// ---------------- problem dims ----------------
#define BATCH   8
#define IMG     224
#define PATCH   16
#define GRIDW   14
#define NPATCH  196          // GRIDW*GRIDW
#define PD      256          // PATCH*PATCH
#define DIM     128
#define DFF     256
#define NCLS    1000
#define MROWS   (BATCH*NPATCH)   // 1568
#define NEG_INF (-3.0e38f)

// ---------------- persistent device scratch (no allocation at runtime) ----------------
__device__ float g_h   [MROWS*DIM];
__device__ float g_xn  [MROWS*DIM];
__device__ float g_q   [MROWS*DIM];
__device__ float g_kt  [BATCH*DIM*NPATCH];
__device__ float g_v   [MROWS*DIM];
__device__ float g_sc  [BATCH*NPATCH*NPATCH];
__device__ float g_attn[MROWS*DIM];
__device__ float g_ffh [MROWS*DFF];
__device__ float g_ff  [MROWS*DIM];
__device__ float g_pool[BATCH*DIM];

__device__ float g_wte[PD*DIM];        // embed_W^T   (256 x 128)
__device__ float g_wtq[DIM*DIM];
__device__ float g_wtk[DIM*DIM];
__device__ float g_wtv[DIM*DIM];
__device__ float g_wt1[DIM*DFF];       // ff1^T (128 x 256)
__device__ float g_wt2[DFF*DIM];       // ff2^T (256 x 128)
__device__ float g_wth[DIM*NCLS];      // head^T (128 x 1000)

// ---------------- weight transpose: W (I x J) -> Wt (J x I) ----------------
__global__ void __launch_bounds__(256) transposeK(const float* __restrict__ W,
                                                  float* __restrict__ Wt, int I, int J)
{
    __shared__ float t[32][33];
    int j0 = blockIdx.x * 32, i0 = blockIdx.y * 32;
    int tx = threadIdx.x, ty = threadIdx.y;
    for (int yy = ty; yy < 32; yy += 8) {
        int i = i0 + yy, j = j0 + tx;
        t[yy][tx] = (i < I && j < J) ? W[(long)i * J + j] : 0.f;
    }
    __syncthreads();
    for (int yy = ty; yy < 32; yy += 8) {
        int j = j0 + yy, i = i0 + tx;
        if (j < J && i < I) Wt[(long)j * I + i] = t[tx][yy];
    }
}

// ---------------- generic tropical GEMM ----------------
// C[b, m, i] = max_j ( A[b, m, j] + Wt[b, j, i] )    (+ mode-specific epilogue)
// MODE 0: plain batched store
// MODE 1: embed (A comes from patchified Xsrc, epilogue adds pos)
// MODE 2: store transposed per batch: kt[b, i, n]
// MODE 3: epilogue max with tau (extra[0])
template<int MODE>
__global__ void __launch_bounds__(128) trop_gemm_k(
    const float* __restrict__ A, const float* __restrict__ Wt, float* __restrict__ Cv,
    int rowsPB, int I, int J, long Abs, long Wbs, long Cbs,
    const float* __restrict__ extra, const float* __restrict__ Xsrc)
{
    __shared__ __align__(16) float As[256 * 8];   // J up to 256, TM = 8
    const int tid = threadIdx.x;
    const int b   = blockIdx.z;
    const int m0  = blockIdx.x * 8;
    const int i   = blockIdx.y * 128 + tid;
    const int ic  = min(i, I - 1);
    const float* Ab = A + (long)b * Abs;
    const float* Wb = Wt + (long)b * Wbs;

    // stage A tile transposed: As[j][r]
    for (int idx = tid; idx < 8 * J; idx += 128) {
        int r = idx / J;
        int j = idx - r * J;
        int m = m0 + r;
        float val = 0.f;
        if (m < rowsPB) {
            if (MODE == 1) {
                int bb = m / NPATCH;
                int n  = m - bb * NPATCH;
                int gy = n / GRIDW, gx = n - gy * GRIDW;
                int py = j >> 4, px = j & 15;
                val = Xsrc[((long)bb * IMG + gy * PATCH + py) * IMG + gx * PATCH + px];
            } else {
                val = Ab[(long)m * J + j];
            }
        }
        As[j * 8 + r] = val;
    }
    __syncthreads();

    float acc[8];
#pragma unroll
    for (int r = 0; r < 8; r++) acc[r] = NEG_INF;

    float w[4];
#pragma unroll
    for (int u = 0; u < 4; u++) w[u] = Wb[(long)u * I + ic];

    for (int j = 0; j < J; j += 4) {
        int jn = min(j + 4, J - 4);           // clamp keeps last prefetch in-bounds
        float nw[4];
#pragma unroll
        for (int u = 0; u < 4; u++) nw[u] = Wb[(long)(jn + u) * I + ic];
#pragma unroll
        for (int u = 0; u < 4; u++) {
            const float4 lo = *(const float4*)(As + (j + u) * 8);
            const float4 hi = *(const float4*)(As + (j + u) * 8 + 4);
            const float wv = w[u];
            acc[0] = fmaxf(acc[0], lo.x + wv);
            acc[1] = fmaxf(acc[1], lo.y + wv);
            acc[2] = fmaxf(acc[2], lo.z + wv);
            acc[3] = fmaxf(acc[3], lo.w + wv);
            acc[4] = fmaxf(acc[4], hi.x + wv);
            acc[5] = fmaxf(acc[5], hi.y + wv);
            acc[6] = fmaxf(acc[6], hi.z + wv);
            acc[7] = fmaxf(acc[7], hi.w + wv);
        }
#pragma unroll
        for (int u = 0; u < 4; u++) w[u] = nw[u];
    }

    if (i < I) {
#pragma unroll
        for (int r = 0; r < 8; r++) {
            int m = m0 + r;
            if (m < rowsPB) {
                float val = acc[r];
                if (MODE == 0) {
                    Cv[(long)b * Cbs + (long)m * I + i] = val;
                } else if (MODE == 1) {
                    int n = m % NPATCH;
                    Cv[(long)m * I + i] = val + extra[(long)n * I + i];
                } else if (MODE == 2) {
                    int bb = m / NPATCH;
                    int n  = m - bb * NPATCH;
                    Cv[(long)bb * (DIM * NPATCH) + (long)i * NPATCH + n] = val;
                } else { // MODE 3
                    Cv[(long)m * I + i] = fmaxf(val, extra[0]);
                }
            }
        }
    }
}

// ---------------- row-wise kernels (one warp per row) ----------------
__global__ void __launch_bounds__(128) pnorm128_k(const float* __restrict__ X, float* __restrict__ Y)
{
    int row  = blockIdx.x * 4 + (threadIdx.x >> 5);
    int lane = threadIdx.x & 31;
    const float* xp = X + (long)row * DIM;
    float v[4];
#pragma unroll
    for (int u = 0; u < 4; u++) v[u] = xp[lane + 32 * u];
    float m = fmaxf(fmaxf(v[0], v[1]), fmaxf(v[2], v[3]));
#pragma unroll
    for (int o = 16; o > 0; o >>= 1) m = fmaxf(m, __shfl_xor_sync(0xffffffffu, m, o));
    float* yp = Y + (long)row * DIM;
#pragma unroll
    for (int u = 0; u < 4; u++) yp[lane + 32 * u] = v[u] - m;
}

__global__ void __launch_bounds__(128) pnorm_sc_k(float* __restrict__ S)
{
    int row  = blockIdx.x * 4 + (threadIdx.x >> 5);
    int lane = threadIdx.x & 31;
    float* sp = S + (long)row * NPATCH;
    float m = NEG_INF;
    for (int e = lane; e < NPATCH; e += 32) m = fmaxf(m, sp[e]);
#pragma unroll
    for (int o = 16; o > 0; o >>= 1) m = fmaxf(m, __shfl_xor_sync(0xffffffffu, m, o));
    for (int e = lane; e < NPATCH; e += 32) sp[e] -= m;
}

// h = max(h, pnorm(raw));  xn = pnorm(h)
__global__ void __launch_bounds__(128) fuse_k(float* __restrict__ H, const float* __restrict__ R,
                                              float* __restrict__ XN)
{
    int row  = blockIdx.x * 4 + (threadIdx.x >> 5);
    int lane = threadIdx.x & 31;
    const float* rp = R + (long)row * DIM;
    float* hp = H + (long)row * DIM;
    float* xp = XN + (long)row * DIM;
    float a[4], hv[4];
#pragma unroll
    for (int u = 0; u < 4; u++) a[u] = rp[lane + 32 * u];
    float am = fmaxf(fmaxf(a[0], a[1]), fmaxf(a[2], a[3]));
#pragma unroll
    for (int o = 16; o > 0; o >>= 1) am = fmaxf(am, __shfl_xor_sync(0xffffffffu, am, o));
#pragma unroll
    for (int u = 0; u < 4; u++) hv[u] = fmaxf(hp[lane + 32 * u], a[u] - am);
    float hm = fmaxf(fmaxf(hv[0], hv[1]), fmaxf(hv[2], hv[3]));
#pragma unroll
    for (int o = 16; o > 0; o >>= 1) hm = fmaxf(hm, __shfl_xor_sync(0xffffffffu, hm, o));
#pragma unroll
    for (int u = 0; u < 4; u++) {
        hp[lane + 32 * u] = hv[u];
        xp[lane + 32 * u] = hv[u] - hm;
    }
}

__global__ void __launch_bounds__(128) pool_k(const float* __restrict__ H, float* __restrict__ P)
{
    int b = blockIdx.x, tid = threadIdx.x;
    const float* hp = H + (long)b * NPATCH * DIM + tid;
    float m = NEG_INF;
    for (int n = 0; n < NPATCH; n++) m = fmaxf(m, hp[(long)n * DIM]);
    P[b * DIM + tid] = m;
}

__global__ void __launch_bounds__(128) head_k(const float* __restrict__ P, const float* __restrict__ Wt,
                                              const float* __restrict__ ls, float* __restrict__ O)
{
    __shared__ float sp[DIM];
    int b = blockIdx.y, tid = threadIdx.x;
    sp[tid] = P[b * DIM + tid];
    __syncthreads();
    int c = blockIdx.x * 128 + tid;
    if (c < NCLS) {
        float acc = NEG_INF;
#pragma unroll 4
        for (int j = 0; j < DIM; j++) acc = fmaxf(acc, sp[j] + Wt[(long)j * NCLS + c]);
        O[(long)b * NCLS + c] = acc * ls[0];
    }
}

// ---------------- launch ----------------
extern "C" void kernel_launch(void* const* d_in, const int* in_sizes, int n_in,
                              void* d_out, int out_size)
{
    (void)in_sizes; (void)n_in; (void)out_size;
    const float* x      = (const float*)d_in[0];
    const float* embedW = (const float*)d_in[1];
    const float* pos    = (const float*)d_in[2];
    const float* W[2][5];
    const float* tau[2];
    for (int l = 0; l < 2; l++) {
        int base = 3 + l * 6;
        for (int k = 0; k < 5; k++) W[l][k] = (const float*)d_in[base + k];
        tau[l] = (const float*)d_in[base + 5];
    }
    const float* headW  = (const float*)d_in[15];
    const float* lscale = (const float*)d_in[16];
    float* out = (float*)d_out;

    float *h, *xn, *q, *kt, *v, *sc, *attn, *ffh, *ff, *pool;
    float *wte, *wtq, *wtk, *wtv, *wt1, *wt2, *wth;
    cudaGetSymbolAddress((void**)&h,    g_h);
    cudaGetSymbolAddress((void**)&xn,   g_xn);
    cudaGetSymbolAddress((void**)&q,    g_q);
    cudaGetSymbolAddress((void**)&kt,   g_kt);
    cudaGetSymbolAddress((void**)&v,    g_v);
    cudaGetSymbolAddress((void**)&sc,   g_sc);
    cudaGetSymbolAddress((void**)&attn, g_attn);
    cudaGetSymbolAddress((void**)&ffh,  g_ffh);
    cudaGetSymbolAddress((void**)&ff,   g_ff);
    cudaGetSymbolAddress((void**)&pool, g_pool);
    cudaGetSymbolAddress((void**)&wte,  g_wte);
    cudaGetSymbolAddress((void**)&wtq,  g_wtq);
    cudaGetSymbolAddress((void**)&wtk,  g_wtk);
    cudaGetSymbolAddress((void**)&wtv,  g_wtv);
    cudaGetSymbolAddress((void**)&wt1,  g_wt1);
    cudaGetSymbolAddress((void**)&wt2,  g_wt2);
    cudaGetSymbolAddress((void**)&wth,  g_wth);

    dim3 tb(32, 8);

    // embed (patchify fused) + pos
    transposeK<<<dim3(8, 4), tb>>>(embedW, wte, DIM, PD);
    trop_gemm_k<1><<<dim3(196, 1, 1), 128>>>(nullptr, wte, h, MROWS, DIM, PD, 0, 0, 0, pos, x);
    pnorm128_k<<<392, 128>>>(h, xn);

    for (int l = 0; l < 2; l++) {
        transposeK<<<dim3(4, 4), tb>>>(W[l][0], wtq, DIM, DIM);
        transposeK<<<dim3(4, 4), tb>>>(W[l][1], wtk, DIM, DIM);
        transposeK<<<dim3(4, 4), tb>>>(W[l][2], wtv, DIM, DIM);
        transposeK<<<dim3(4, 8), tb>>>(W[l][3], wt1, DFF, DIM);
        transposeK<<<dim3(8, 4), tb>>>(W[l][4], wt2, DIM, DFF);

        // q, kt, v from xn
        trop_gemm_k<0><<<dim3(196, 1, 1), 128>>>(xn, wtq, q,  MROWS, DIM, DIM, 0, 0, 0, nullptr, nullptr);
        trop_gemm_k<2><<<dim3(196, 1, 1), 128>>>(xn, wtk, kt, MROWS, DIM, DIM, 0, 0, 0, nullptr, nullptr);
        trop_gemm_k<0><<<dim3(196, 1, 1), 128>>>(xn, wtv, v,  MROWS, DIM, DIM, 0, 0, 0, nullptr, nullptr);

        // scores[b,i,j] = max_d(q + kt), then row pnorm
        trop_gemm_k<0><<<dim3(25, 2, 8), 128>>>(q, kt, sc, NPATCH, NPATCH, DIM,
                                                (long)NPATCH * DIM, (long)DIM * NPATCH,
                                                (long)NPATCH * NPATCH, nullptr, nullptr);
        pnorm_sc_k<<<392, 128>>>(sc);

        // attn[b,i,d] = max_j(scores + v)
        trop_gemm_k<0><<<dim3(25, 1, 8), 128>>>(sc, v, attn, NPATCH, DIM, NPATCH,
                                                (long)NPATCH * NPATCH, (long)NPATCH * DIM,
                                                (long)NPATCH * DIM, nullptr, nullptr);
        fuse_k<<<392, 128>>>(h, attn, xn);

        // ff
        trop_gemm_k<3><<<dim3(196, 2, 1), 128>>>(xn, wt1, ffh, MROWS, DFF, DIM, 0, 0, 0, tau[l], nullptr);
        trop_gemm_k<0><<<dim3(196, 1, 1), 128>>>(ffh, wt2, ff, MROWS, DIM, DFF, 0, 0, 0, nullptr, nullptr);
        fuse_k<<<392, 128>>>(h, ff, xn);
    }

    pool_k<<<8, 128>>>(h, pool);
    transposeK<<<dim3(4, 32), tb>>>(headW, wth, NCLS, DIM);
    head_k<<<dim3(8, 8), 128>>>(pool, wth, lscale, out);
}

// round 2
// speedup vs baseline: 2.0253x; 2.0253x over previous
#include <cuda_runtime.h>

// ---------------- dims ----------------
#define BATCH   8
#define IMG     224
#define PATCH   16
#define GRIDW   14
#define NPATCH  196
#define PD      256
#define DIM     128
#define DFF     256
#define NCLS    1000
#define MROWS   (BATCH*NPATCH)   // 1568
#define NEG_INF (-3.0e38f)

typedef unsigned long long u64;

// ---------------- packed f32x2 helpers ----------------
__device__ __forceinline__ u64 pk2(float lo, float hi) {
    u64 r;
    asm("mov.b64 %0,{%1,%2};" : "=l"(r) : "r"(__float_as_uint(lo)), "r"(__float_as_uint(hi)));
    return r;
}
__device__ __forceinline__ u64 addx2(u64 a, u64 b) {
    u64 r;
    asm("add.rn.f32x2 %0,%1,%2;" : "=l"(r) : "l"(a), "l"(b));
    return r;
}
__device__ __forceinline__ void upk2(u64 v, float& a, float& b) {
    unsigned x, y;
    asm("mov.b64 {%0,%1},%2;" : "=r"(x), "=r"(y) : "l"(v));
    a = __uint_as_float(x); b = __uint_as_float(y);
}

// ---------------- persistent scratch ----------------
__device__ float g_h   [MROWS*DIM];
__device__ float g_xn  [MROWS*DIM];
__device__ float g_q   [MROWS*DIM];
__device__ float g_kt4 [BATCH*DIM*NPATCH];
__device__ float g_v4  [BATCH*NPATCH*DIM];
__device__ float g_sc  [BATCH*NPATCH*NPATCH];
__device__ float g_rm  [BATCH*NPATCH];
__device__ float g_ffh [MROWS*DFF];
__device__ float g_pool[BATCH*DIM];

// blocked weights: Wt4[((j>>2)*I + i)*4 + (j&3)] = W[i*J + j]
__device__ float g_wte4[PD*DIM];
__device__ float g_wtq4[2*DIM*DIM];
__device__ float g_wtk4[2*DIM*DIM];
__device__ float g_wtv4[2*DIM*DIM];
__device__ float g_wt14[2*DFF*DIM];
__device__ float g_wt24[2*DIM*DFF];
__device__ float g_wth4[NCLS*DIM];

// ---------------- prep: transpose+block ALL weights in one launch ----------------
struct TJ { const float* src; float* dst; int I, J, base; };
struct TJobs { TJ j[12]; };

__global__ void __launch_bounds__(256) prep_k(TJobs jobs)
{
    __shared__ float tbuf[32][33];
    int b = blockIdx.x;
    int k = 0;
#pragma unroll
    for (int t = 1; t < 12; t++) if (jobs.j[t].base <= b) k = t;
    const TJ job = jobs.j[k];
    int t = b - job.base;
    int txt = (job.J + 31) / 32;
    int j0 = (t % txt) * 32, i0 = (t / txt) * 32;
    int tx = threadIdx.x & 31, ty = threadIdx.x >> 5;
    for (int yy = ty; yy < 32; yy += 8) {
        int i = i0 + yy, j = j0 + tx;
        tbuf[yy][tx] = (i < job.I && j < job.J) ? job.src[(long)i * job.J + j] : 0.f;
    }
    __syncthreads();
    for (int yy = ty; yy < 32; yy += 8) {
        int j = j0 + yy, i = i0 + tx;
        if (j < job.J && i < job.I)
            job.dst[((long)(j >> 2) * job.I + i) * 4 + (j & 3)] = tbuf[tx][yy];
    }
}

// ---------------- tropical GEMM core ----------------
// acc[r] = max_j ( A[m0+r, j] + W[ic, j] ),  W in blocked float4 layout
template<int NT, int J, bool PSTAGE>
__device__ __forceinline__ void trop_core(
    const float* __restrict__ Ab, const float4* __restrict__ W4,
    float* As, int I, int rowsPB, int m0, int ic, float acc[8])
{
    const int tid = threadIdx.x;
    for (int idx = tid; idx < 8 * J; idx += NT) {
        int r = idx / J, j = idx - r * J;
        int m = m0 + r;
        float val = 0.f;
        if (m < rowsPB) {
            if (PSTAGE) {
                int bb = m / NPATCH, n = m - bb * NPATCH;
                int gy = n / GRIDW, gx = n - gy * GRIDW;
                val = Ab[((long)bb * IMG + gy * PATCH + (j >> 4)) * IMG + gx * PATCH + (j & 15)];
            } else {
                val = Ab[(long)m * J + j];
            }
        }
        As[j * 8 + r] = val;
    }
    __syncthreads();
#pragma unroll
    for (int r = 0; r < 8; r++) acc[r] = NEG_INF;

    float4 w = W4[ic];
#pragma unroll 4
    for (int j = 0; j < J; j += 4) {
        int jn = min(j + 4, J - 4);
        float4 nw = W4[(jn >> 2) * I + ic];
        float wv[4] = { w.x, w.y, w.z, w.w };
#pragma unroll
        for (int u = 0; u < 4; u++) {
            u64 w2 = pk2(wv[u], wv[u]);
            const ulonglong2* ap = (const ulonglong2*)(As + (j + u) * 8);
            ulonglong2 p0 = ap[0], p1 = ap[1];
            u64 t0 = addx2(p0.x, w2), t1 = addx2(p0.y, w2);
            u64 t2 = addx2(p1.x, w2), t3 = addx2(p1.y, w2);
            float a, b;
            upk2(t0, a, b); acc[0] = fmaxf(acc[0], a); acc[1] = fmaxf(acc[1], b);
            upk2(t1, a, b); acc[2] = fmaxf(acc[2], a); acc[3] = fmaxf(acc[3], b);
            upk2(t2, a, b); acc[4] = fmaxf(acc[4], a); acc[5] = fmaxf(acc[5], b);
            upk2(t3, a, b); acc[6] = fmaxf(acc[6], a); acc[7] = fmaxf(acc[7], b);
        }
        w = nw;
    }
}

// block-wide per-row max of 8 accumulators (valid=false excludes this thread)
template<int NT>
__device__ __forceinline__ void blk_rowmax(float* red, const float vin[8], float rm[8], bool valid)
{
    const int NW = NT / 32;
    int tid = threadIdx.x, lane = tid & 31, wid = tid >> 5;
    float v[8];
#pragma unroll
    for (int r = 0; r < 8; r++) {
        v[r] = valid ? vin[r] : NEG_INF;
#pragma unroll
        for (int o = 16; o > 0; o >>= 1) v[r] = fmaxf(v[r], __shfl_xor_sync(0xffffffffu, v[r], o));
    }
    __syncthreads();
    if (lane == 0) {
#pragma unroll
        for (int r = 0; r < 8; r++) red[r * NW + wid] = v[r];
    }
    __syncthreads();
#pragma unroll
    for (int r = 0; r < 8; r++) {
        float m = red[r * NW];
#pragma unroll
        for (int w = 1; w < NW; w++) m = fmaxf(m, red[r * NW + w]);
        rm[r] = m;
    }
}

// ---------------- fused kernels ----------------

// embed: patchify -> trop_mm -> +pos -> pnorm ; writes h, xn
__global__ void __launch_bounds__(128) embed_k(
    const float* __restrict__ x, const float* __restrict__ wte4, const float* __restrict__ pos,
    float* __restrict__ h, float* __restrict__ xn)
{
    __shared__ __align__(16) float As[PD * 8];
    __shared__ float red[8 * 4];
    int m0 = blockIdx.x * 8, i = threadIdx.x;
    float acc[8];
    trop_core<128, PD, true>(x, (const float4*)wte4, As, DIM, MROWS, m0, i, acc);
#pragma unroll
    for (int r = 0; r < 8; r++) {
        int m = m0 + r, n = m - (m / NPATCH) * NPATCH;
        acc[r] += pos[n * DIM + i];
    }
    float rm[8];
    blk_rowmax<128>(red, acc, rm, true);
#pragma unroll
    for (int r = 0; r < 8; r++) {
        int m = m0 + r;
        h[(long)m * DIM + i] = acc[r];
        xn[(long)m * DIM + i] = acc[r] - rm[r];
    }
}

// q/k/v in one launch; blockIdx.y selects weight/destination.
// k stored blocked [(d>>2)*N + n]*4+(d&3) per batch; v stored blocked [(n>>2)*D + d]*4+(n&3).
__global__ void __launch_bounds__(128) qkv_k(
    const float* __restrict__ xn, const float* __restrict__ wq4, const float* __restrict__ wk4,
    const float* __restrict__ wv4, float* __restrict__ q, float* __restrict__ kt4, float* __restrict__ v4)
{
    __shared__ __align__(16) float As[DIM * 8];
    int m0 = blockIdx.x * 8, i = threadIdx.x, y = blockIdx.y;
    const float* W4 = (y == 0) ? wq4 : (y == 1) ? wk4 : wv4;
    float acc[8];
    trop_core<128, DIM, false>(xn, (const float4*)W4, As, DIM, MROWS, m0, i, acc);
#pragma unroll
    for (int r = 0; r < 8; r++) {
        int m = m0 + r;
        if (y == 0) {
            q[(long)m * DIM + i] = acc[r];
        } else {
            int b = m / NPATCH, n = m - b * NPATCH;
            if (y == 1) kt4[(long)b * DIM * NPATCH + ((i >> 2) * NPATCH + n) * 4 + (i & 3)] = acc[r];
            else        v4 [(long)b * NPATCH * DIM + ((n >> 2) * DIM + i) * 4 + (n & 3)] = acc[r];
        }
    }
}

// scores: sc[b,i,j] = max_d(q+k) raw, plus per-row max rm
__global__ void __launch_bounds__(224) scores_k(
    const float* __restrict__ q, const float* __restrict__ kt4,
    float* __restrict__ sc, float* __restrict__ rmo)
{
    __shared__ __align__(16) float As[DIM * 8];
    __shared__ float red[8 * 7];
    int b = blockIdx.z, m0 = blockIdx.x * 8, i = threadIdx.x;
    int ic = min(i, NPATCH - 1);
    float acc[8];
    trop_core<224, DIM, false>(q + (long)b * NPATCH * DIM,
                               (const float4*)(kt4 + (long)b * DIM * NPATCH),
                               As, NPATCH, NPATCH, m0, ic, acc);
    bool valid = (i < NPATCH);
    float rm[8];
    blk_rowmax<224>(red, acc, rm, valid);
#pragma unroll
    for (int r = 0; r < 8; r++) {
        int m = m0 + r;
        if (m < NPATCH && valid) sc[((long)b * NPATCH + m) * NPATCH + i] = acc[r];
    }
    if (threadIdx.x == 0) {
#pragma unroll
        for (int r = 0; r < 8; r++) {
            int m = m0 + r;
            if (m < NPATCH) rmo[b * NPATCH + m] = rm[r];
        }
    }
}

// attn: out = max_j(sc+v) - rm ; pnorm ; h=max(h,.) ; xn=pnorm(h)
__global__ void __launch_bounds__(128) attn_k(
    const float* __restrict__ sc, const float* __restrict__ v4, const float* __restrict__ rmv,
    float* __restrict__ h, float* __restrict__ xn)
{
    __shared__ __align__(16) float As[NPATCH * 8];
    __shared__ float red[8 * 4];
    int b = blockIdx.z, m0 = blockIdx.x * 8, i = threadIdx.x;
    float acc[8];
    trop_core<128, NPATCH, false>(sc + (long)b * NPATCH * NPATCH,
                                  (const float4*)(v4 + (long)b * NPATCH * DIM),
                                  As, DIM, NPATCH, m0, i, acc);
    float av[8];
#pragma unroll
    for (int r = 0; r < 8; r++) {
        int m = m0 + r;
        av[r] = (m < NPATCH) ? acc[r] - rmv[b * NPATCH + m] : NEG_INF;
    }
    float am[8];
    blk_rowmax<128>(red, av, am, true);
    float hv[8];
#pragma unroll
    for (int r = 0; r < 8; r++) {
        int m = m0 + r;
        if (m < NPATCH) {
            long row = (long)b * NPATCH + m;
            hv[r] = fmaxf(h[row * DIM + i], av[r] - am[r]);
        } else hv[r] = NEG_INF;
    }
    float hm[8];
    blk_rowmax<128>(red, hv, hm, true);
#pragma unroll
    for (int r = 0; r < 8; r++) {
        int m = m0 + r;
        if (m < NPATCH) {
            long row = (long)b * NPATCH + m;
            h[row * DIM + i] = hv[r];
            xn[row * DIM + i] = hv[r] - hm[r];
        }
    }
}

// ff1: ffh = max(trop_mm(xn, ff1W), tau)
__global__ void __launch_bounds__(128) ff1_k(
    const float* __restrict__ xn, const float* __restrict__ w4,
    const float* __restrict__ tau, float* __restrict__ ffh)
{
    __shared__ __align__(16) float As[DIM * 8];
    int m0 = blockIdx.x * 8, i = blockIdx.y * 128 + threadIdx.x;
    float acc[8];
    trop_core<128, DIM, false>(xn, (const float4*)w4, As, DFF, MROWS, m0, i, acc);
    float tv = tau[0];
#pragma unroll
    for (int r = 0; r < 8; r++) {
        int m = m0 + r;
        ffh[(long)m * DFF + i] = fmaxf(acc[r], tv);
    }
}

// ff2: ff = trop_mm(ffh, ff2W) ; pnorm ; h=max(h,.) ; xn=pnorm(h)
__global__ void __launch_bounds__(128) ff2_k(
    const float* __restrict__ ffh, const float* __restrict__ w4,
    float* __restrict__ h, float* __restrict__ xn)
{
    __shared__ __align__(16) float As[DFF * 8];
    __shared__ float red[8 * 4];
    int m0 = blockIdx.x * 8, i = threadIdx.x;
    float acc[8];
    trop_core<128, DFF, false>(ffh, (const float4*)w4, As, DIM, MROWS, m0, i, acc);
    float am[8];
    blk_rowmax<128>(red, acc, am, true);
    float hv[8];
#pragma unroll
    for (int r = 0; r < 8; r++) {
        int m = m0 + r;
        hv[r] = fmaxf(h[(long)m * DIM + i], acc[r] - am[r]);
    }
    float hm[8];
    blk_rowmax<128>(red, hv, hm, true);
#pragma unroll
    for (int r = 0; r < 8; r++) {
        int m = m0 + r;
        h[(long)m * DIM + i] = hv[r];
        xn[(long)m * DIM + i] = hv[r] - hm[r];
    }
}

__global__ void __launch_bounds__(128) pool_k(const float* __restrict__ H, float* __restrict__ P)
{
    int b = blockIdx.x, tid = threadIdx.x;
    const float* hp = H + (long)b * NPATCH * DIM + tid;
    float m = NEG_INF;
#pragma unroll 4
    for (int n = 0; n < NPATCH; n++) m = fmaxf(m, hp[(long)n * DIM]);
    P[b * DIM + tid] = m;
}

__global__ void __launch_bounds__(128) head_k(
    const float* __restrict__ P, const float* __restrict__ w4,
    const float* __restrict__ ls, float* __restrict__ O)
{
    __shared__ float sp[DIM];
    int b = blockIdx.y, tid = threadIdx.x;
    sp[tid] = P[b * DIM + tid];
    __syncthreads();
    int c = blockIdx.x * 128 + tid;
    if (c < NCLS) {
        const float4* W = (const float4*)w4;
        float acc = NEG_INF;
#pragma unroll 4
        for (int j = 0; j < DIM; j += 4) {
            float4 w = W[(j >> 2) * NCLS + c];
            acc = fmaxf(acc, sp[j + 0] + w.x);
            acc = fmaxf(acc, sp[j + 1] + w.y);
            acc = fmaxf(acc, sp[j + 2] + w.z);
            acc = fmaxf(acc, sp[j + 3] + w.w);
        }
        O[(long)b * NCLS + c] = acc * ls[0];
    }
}

// ---------------- launch ----------------
extern "C" void kernel_launch(void* const* d_in, const int* in_sizes, int n_in,
                              void* d_out, int out_size)
{
    (void)in_sizes; (void)n_in; (void)out_size;
    const float* x      = (const float*)d_in[0];
    const float* embedW = (const float*)d_in[1];
    const float* pos    = (const float*)d_in[2];
    const float* W[2][5];
    const float* tau[2];
    for (int l = 0; l < 2; l++) {
        int base = 3 + l * 6;
        for (int k = 0; k < 5; k++) W[l][k] = (const float*)d_in[base + k];
        tau[l] = (const float*)d_in[base + 5];
    }
    const float* headW  = (const float*)d_in[15];
    const float* lscale = (const float*)d_in[16];
    float* out = (float*)d_out;

    float *h, *xn, *q, *kt4, *v4, *sc, *rm, *ffh, *pool;
    float *wte4, *wtq4, *wtk4, *wtv4, *wt14, *wt24, *wth4;
    cudaGetSymbolAddress((void**)&h,    g_h);
    cudaGetSymbolAddress((void**)&xn,   g_xn);
    cudaGetSymbolAddress((void**)&q,    g_q);
    cudaGetSymbolAddress((void**)&kt4,  g_kt4);
    cudaGetSymbolAddress((void**)&v4,   g_v4);
    cudaGetSymbolAddress((void**)&sc,   g_sc);
    cudaGetSymbolAddress((void**)&rm,   g_rm);
    cudaGetSymbolAddress((void**)&ffh,  g_ffh);
    cudaGetSymbolAddress((void**)&pool, g_pool);
    cudaGetSymbolAddress((void**)&wte4, g_wte4);
    cudaGetSymbolAddress((void**)&wtq4, g_wtq4);
    cudaGetSymbolAddress((void**)&wtk4, g_wtk4);
    cudaGetSymbolAddress((void**)&wtv4, g_wtv4);
    cudaGetSymbolAddress((void**)&wt14, g_wt14);
    cudaGetSymbolAddress((void**)&wt24, g_wt24);
    cudaGetSymbolAddress((void**)&wth4, g_wth4);

    // build transpose jobs
    TJobs jobs;
    int base = 0, nj = 0;
    auto addJob = [&](const float* s, float* d, int I, int J) {
        jobs.j[nj].src = s; jobs.j[nj].dst = d; jobs.j[nj].I = I; jobs.j[nj].J = J;
        jobs.j[nj].base = base;
        base += ((J + 31) / 32) * ((I + 31) / 32);
        nj++;
    };
    addJob(embedW, wte4, DIM, PD);
    for (int l = 0; l < 2; l++) {
        addJob(W[l][0], wtq4 + l * DIM * DIM, DIM, DIM);
        addJob(W[l][1], wtk4 + l * DIM * DIM, DIM, DIM);
        addJob(W[l][2], wtv4 + l * DIM * DIM, DIM, DIM);
        addJob(W[l][3], wt14 + l * DFF * DIM, DFF, DIM);
        addJob(W[l][4], wt24 + l * DIM * DFF, DIM, DFF);
    }
    addJob(headW, wth4, NCLS, DIM);

    prep_k<<<base, 256>>>(jobs);
    embed_k<<<196, 128>>>(x, wte4, pos, h, xn);

    for (int l = 0; l < 2; l++) {
        qkv_k<<<dim3(196, 3), 128>>>(xn, wtq4 + l * DIM * DIM, wtk4 + l * DIM * DIM,
                                     wtv4 + l * DIM * DIM, q, kt4, v4);
        scores_k<<<dim3(25, 1, 8), 224>>>(q, kt4, sc, rm);
        attn_k<<<dim3(25, 1, 8), 128>>>(sc, v4, rm, h, xn);
        ff1_k<<<dim3(196, 2), 128>>>(xn, wt14 + l * DFF * DIM, tau[l], ffh);
        ff2_k<<<196, 128>>>(ffh, wt24 + l * DIM * DFF, h, xn);
    }

    pool_k<<<8, 128>>>(h, pool);
    head_k<<<dim3(8, 8), 128>>>(pool, wth4, lscale, out);
}

// round 5
// speedup vs baseline: 2.7426x; 1.3542x over previous
#include <cuda_runtime.h>

// ---------------- dims ----------------
#define BATCH   8
#define IMG     224
#define PATCH   16
#define GRIDW   14
#define NPATCH  196
#define PD      256
#define DIM     128
#define DFF     256
#define NCLS    1000
#define MROWS   (BATCH*NPATCH)   // 1568
#define NEG_INF (-3.0e38f)

typedef unsigned long long u64;

// ---------------- packed f32x2 helpers ----------------
__device__ __forceinline__ u64 pk2(float lo, float hi) {
    u64 r;
    asm("mov.b64 %0,{%1,%2};" : "=l"(r) : "r"(__float_as_uint(lo)), "r"(__float_as_uint(hi)));
    return r;
}
__device__ __forceinline__ u64 addx2(u64 a, u64 b) {
    u64 r;
    asm("add.rn.f32x2 %0,%1,%2;" : "=l"(r) : "l"(a), "l"(b));
    return r;
}
__device__ __forceinline__ void upk2(u64 v, float& a, float& b) {
    unsigned x, y;
    asm("mov.b64 {%0,%1},%2;" : "=r"(x), "=r"(y) : "l"(v));
    a = __uint_as_float(x); b = __uint_as_float(y);
}

// ---------------- persistent scratch ----------------
__device__ float g_h   [MROWS*DIM];
__device__ float g_xn  [MROWS*DIM];
__device__ float g_q   [MROWS*DIM];
__device__ float g_kt4 [BATCH*DIM*NPATCH];
__device__ float g_v4  [BATCH*NPATCH*DIM];
__device__ float g_ffh [MROWS*DFF];
__device__ float g_poolp[BATCH*7*DIM];

// blocked weights: Wt4[((j>>2)*I + i)*4 + (j&3)] = W[i*J + j]
__device__ float g_wte4[PD*DIM];
__device__ float g_wtq4[2*DIM*DIM];
__device__ float g_wtk4[2*DIM*DIM];
__device__ float g_wtv4[2*DIM*DIM];
__device__ float g_wt14[2*DFF*DIM];
__device__ float g_wt24[2*DIM*DFF];
__device__ float g_wth4[NCLS*DIM];

// ---------------- prep: transpose+block ALL weights in one launch ----------------
struct TJ { const float* src; float* dst; int I, J, base; };
struct TJobs { TJ j[12]; };

__global__ void __launch_bounds__(256) prep_k(TJobs jobs)
{
    __shared__ float tbuf[32][33];
    int b = blockIdx.x;
    int k = 0;
#pragma unroll
    for (int t = 1; t < 12; t++) if (jobs.j[t].base <= b) k = t;
    const TJ job = jobs.j[k];
    int t = b - job.base;
    int txt = (job.J + 31) / 32;
    int j0 = (t % txt) * 32, i0 = (t / txt) * 32;
    int tx = threadIdx.x & 31, ty = threadIdx.x >> 5;
    for (int yy = ty; yy < 32; yy += 8) {
        int i = i0 + yy, j = j0 + tx;
        tbuf[yy][tx] = (i < job.I && j < job.J) ? job.src[(long)i * job.J + j] : 0.f;
    }
    __syncthreads();
    for (int yy = ty; yy < 32; yy += 8) {
        int j = j0 + yy, i = i0 + tx;
        if (j < job.J && i < job.I)
            job.dst[((long)(j >> 2) * job.I + i) * 4 + (j & 3)] = tbuf[tx][yy];
    }
}

// ---------------- tropical GEMM core, TM=4 ----------------
// acc[r] = max_j ( A[m0+r, j] + W[ic, j] ),  W in blocked float4 layout
template<int NT, int J, bool PSTAGE>
__device__ __forceinline__ void trop_core4(
    const float* __restrict__ Ab, const float4* __restrict__ W4,
    float* As, int I, int m0, int ic, float acc[4])
{
    const int tid = threadIdx.x;
#pragma unroll
    for (int idx = tid; idx < 4 * J; idx += NT) {
        int r = idx / J, j = idx - r * J;
        int m = m0 + r;
        float val;
        if (PSTAGE) {
            int bb = m / NPATCH, n = m - bb * NPATCH;
            int gy = n / GRIDW, gx = n - gy * GRIDW;
            val = Ab[((long)bb * IMG + gy * PATCH + (j >> 4)) * IMG + gx * PATCH + (j & 15)];
        } else {
            val = Ab[(long)m * J + j];
        }
        As[j * 4 + r] = val;
    }
    __syncthreads();
#pragma unroll
    for (int r = 0; r < 4; r++) acc[r] = NEG_INF;

    float4 w = W4[ic];
#pragma unroll 4
    for (int j = 0; j < J; j += 4) {
        int jn = min(j + 4, J - 4);
        float4 nw = W4[(jn >> 2) * I + ic];
        float wv[4] = { w.x, w.y, w.z, w.w };
#pragma unroll
        for (int u = 0; u < 4; u++) {
            u64 w2 = pk2(wv[u], wv[u]);
            ulonglong2 p = *(const ulonglong2*)(As + (j + u) * 4);
            u64 t0 = addx2(p.x, w2), t1 = addx2(p.y, w2);
            float a, b;
            upk2(t0, a, b); acc[0] = fmaxf(acc[0], a); acc[1] = fmaxf(acc[1], b);
            upk2(t1, a, b); acc[2] = fmaxf(acc[2], a); acc[3] = fmaxf(acc[3], b);
        }
        w = nw;
    }
}

// block-wide per-row max of 4 accumulators (valid=false excludes this thread)
template<int NT>
__device__ __forceinline__ void blk_rowmax4(float* red, const float vin[4], float rm[4], bool valid)
{
    const int NW = NT / 32;
    int tid = threadIdx.x, lane = tid & 31, wid = tid >> 5;
    float v[4];
#pragma unroll
    for (int r = 0; r < 4; r++) {
        v[r] = valid ? vin[r] : NEG_INF;
#pragma unroll
        for (int o = 16; o > 0; o >>= 1) v[r] = fmaxf(v[r], __shfl_xor_sync(0xffffffffu, v[r], o));
    }
    __syncthreads();
    if (lane == 0) {
#pragma unroll
        for (int r = 0; r < 4; r++) red[r * NW + wid] = v[r];
    }
    __syncthreads();
#pragma unroll
    for (int r = 0; r < 4; r++) {
        float m = red[r * NW];
#pragma unroll
        for (int w = 1; w < NW; w++) m = fmaxf(m, red[r * NW + w]);
        rm[r] = m;
    }
}

// ---------------- fused kernels ----------------

// embed: patchify -> trop_mm -> +pos -> pnorm ; writes h, xn
__global__ void __launch_bounds__(128) embed_k(
    const float* __restrict__ x, const float* __restrict__ wte4, const float* __restrict__ pos,
    float* __restrict__ h, float* __restrict__ xn)
{
    __shared__ __align__(16) float As[PD * 4];
    __shared__ float red[4 * 4];
    int m0 = blockIdx.x * 4, i = threadIdx.x;
    float acc[4];
    trop_core4<128, PD, true>(x, (const float4*)wte4, As, DIM, m0, i, acc);
#pragma unroll
    for (int r = 0; r < 4; r++) {
        int m = m0 + r, n = m - (m / NPATCH) * NPATCH;
        acc[r] += pos[n * DIM + i];
    }
    float rm[4];
    blk_rowmax4<128>(red, acc, rm, true);
#pragma unroll
    for (int r = 0; r < 4; r++) {
        int m = m0 + r;
        h[(long)m * DIM + i] = acc[r];
        xn[(long)m * DIM + i] = acc[r] - rm[r];
    }
}

// q/k/v in one launch; blockIdx.y selects weight/destination.
__global__ void __launch_bounds__(128) qkv_k(
    const float* __restrict__ xn, const float* __restrict__ wq4, const float* __restrict__ wk4,
    const float* __restrict__ wv4, float* __restrict__ q, float* __restrict__ kt4, float* __restrict__ v4)
{
    __shared__ __align__(16) float As[DIM * 4];
    int m0 = blockIdx.x * 4, i = threadIdx.x, y = blockIdx.y;
    const float* W4 = (y == 0) ? wq4 : (y == 1) ? wk4 : wv4;
    float acc[4];
    trop_core4<128, DIM, false>(xn, (const float4*)W4, As, DIM, m0, i, acc);
#pragma unroll
    for (int r = 0; r < 4; r++) {
        int m = m0 + r;
        if (y == 0) {
            q[(long)m * DIM + i] = acc[r];
        } else {
            int b = m / NPATCH, n = m - b * NPATCH;
            if (y == 1) kt4[(long)b * DIM * NPATCH + ((i >> 2) * NPATCH + n) * 4 + (i & 3)] = acc[r];
            else        v4 [(long)b * NPATCH * DIM + ((n >> 2) * DIM + i) * 4 + (n & 3)] = acc[r];
        }
    }
}

// fused scores+attn: block = 4 score rows of one batch, 256 threads
// phase1: sc[m, j] = max_d(q+k)   (thread-per-column j over 196)
// phase2: out[m, d] = max_j(sc+v) - rm ; pnorm ; h=max(h,.) ; xn=pnorm(h)
__global__ void __launch_bounds__(256) sa_k(
    const float* __restrict__ q, const float* __restrict__ kt4, const float* __restrict__ v4,
    float* __restrict__ h, float* __restrict__ xn)
{
    __shared__ __align__(16) float qs[DIM * 4];
    __shared__ __align__(16) float scs[NPATCH * 4];
    __shared__ __align__(16) float part[DIM * 4];
    __shared__ float red[4 * 8];
    const int b = blockIdx.y, m0 = blockIdx.x * 4;   // rows within batch (196 % 4 == 0)
    const int tid = threadIdx.x;

    // ---- phase 1: scores ----
    const int i = tid;
    const bool valid = (i < NPATCH);
    const int ic = min(i, NPATCH - 1);
    float acc[4];
    trop_core4<256, DIM, false>(q + (long)b * NPATCH * DIM,
                                (const float4*)(kt4 + (long)b * DIM * NPATCH),
                                qs, NPATCH, m0, ic, acc);
    float rm[4];
    blk_rowmax4<256>(red, acc, rm, valid);
    if (valid) *(float4*)(scs + i * 4) = make_float4(acc[0], acc[1], acc[2], acc[3]);
    __syncthreads();

    // ---- phase 2: attention output, j-range split across two thread-halves ----
    const int d = tid & 127, hh = tid >> 7;
    const int j0 = hh ? 100 : 0, j1 = hh ? 196 : 100;
    const float4* V4 = (const float4*)(v4 + (long)b * NPATCH * DIM);
    float pacc[4];
#pragma unroll
    for (int r = 0; r < 4; r++) pacc[r] = NEG_INF;
    for (int j = j0; j < j1; j += 4) {
        float4 v = V4[(j >> 2) * DIM + d];
        float vv[4] = { v.x, v.y, v.z, v.w };
#pragma unroll
        for (int u = 0; u < 4; u++) {
            u64 v2 = pk2(vv[u], vv[u]);
            ulonglong2 p = *(const ulonglong2*)(scs + (j + u) * 4);
            u64 t0 = addx2(p.x, v2), t1 = addx2(p.y, v2);
            float a, bb;
            upk2(t0, a, bb); pacc[0] = fmaxf(pacc[0], a); pacc[1] = fmaxf(pacc[1], bb);
            upk2(t1, a, bb); pacc[2] = fmaxf(pacc[2], a); pacc[3] = fmaxf(pacc[3], bb);
        }
    }
    if (hh) *(float4*)(part + d * 4) = make_float4(pacc[0], pacc[1], pacc[2], pacc[3]);
    __syncthreads();
    float av[4];
    if (!hh) {
        float4 o = *(const float4*)(part + d * 4);
        av[0] = fmaxf(pacc[0], o.x) - rm[0];
        av[1] = fmaxf(pacc[1], o.y) - rm[1];
        av[2] = fmaxf(pacc[2], o.z) - rm[2];
        av[3] = fmaxf(pacc[3], o.w) - rm[3];
    } else {
#pragma unroll
        for (int r = 0; r < 4; r++) av[r] = NEG_INF;
    }
    float am[4];
    blk_rowmax4<256>(red, av, am, !hh);
    float hv[4];
    if (!hh) {
#pragma unroll
        for (int r = 0; r < 4; r++) {
            long row = (long)b * NPATCH + m0 + r;
            hv[r] = fmaxf(h[row * DIM + d], av[r] - am[r]);
        }
    } else {
#pragma unroll
        for (int r = 0; r < 4; r++) hv[r] = NEG_INF;
    }
    float hm[4];
    blk_rowmax4<256>(red, hv, hm, !hh);
    if (!hh) {
#pragma unroll
        for (int r = 0; r < 4; r++) {
            long row = (long)b * NPATCH + m0 + r;
            h[row * DIM + d] = hv[r];
            xn[row * DIM + d] = hv[r] - hm[r];
        }
    }
}

// ff1: ffh = max(trop_mm(xn, ff1W), tau)
__global__ void __launch_bounds__(128) ff1_k(
    const float* __restrict__ xn, const float* __restrict__ w4,
    const float* __restrict__ tau, float* __restrict__ ffh)
{
    __shared__ __align__(16) float As[DIM * 4];
    int m0 = blockIdx.x * 4, i = blockIdx.y * 128 + threadIdx.x;
    float acc[4];
    trop_core4<128, DIM, false>(xn, (const float4*)w4, As, DFF, m0, i, acc);
    float tv = tau[0];
#pragma unroll
    for (int r = 0; r < 4; r++) {
        int m = m0 + r;
        ffh[(long)m * DFF + i] = fmaxf(acc[r], tv);
    }
}

// ff2: ff = trop_mm(ffh, ff2W) ; pnorm ; h=max(h,.) ; xn=pnorm(h)
__global__ void __launch_bounds__(128) ff2_k(
    const float* __restrict__ ffh, const float* __restrict__ w4,
    float* __restrict__ h, float* __restrict__ xn)
{
    __shared__ __align__(16) float As[DFF * 4];
    __shared__ float red[4 * 4];
    int m0 = blockIdx.x * 4, i = threadIdx.x;
    float acc[4];
    trop_core4<128, DFF, false>(ffh, (const float4*)w4, As, DIM, m0, i, acc);
    float am[4];
    blk_rowmax4<128>(red, acc, am, true);
    float hv[4];
#pragma unroll
    for (int r = 0; r < 4; r++) {
        int m = m0 + r;
        hv[r] = fmaxf(h[(long)m * DIM + i], acc[r] - am[r]);
    }
    float hm[4];
    blk_rowmax4<128>(red, hv, hm, true);
#pragma unroll
    for (int r = 0; r < 4; r++) {
        int m = m0 + r;
        h[(long)m * DIM + i] = hv[r];
        xn[(long)m * DIM + i] = hv[r] - hm[r];
    }
}

// partial pool over 28-patch chunks: Pp[(b*7+c)*DIM + d]
__global__ void __launch_bounds__(128) pool1_k(const float* __restrict__ H, float* __restrict__ Pp)
{
    int b = blockIdx.x, c = blockIdx.y, tid = threadIdx.x;
    const float* hp = H + ((long)b * NPATCH + c * 28) * DIM + tid;
    float m = NEG_INF;
#pragma unroll 4
    for (int n = 0; n < 28; n++) m = fmaxf(m, hp[(long)n * DIM]);
    Pp[(b * 7 + c) * DIM + tid] = m;
}

__global__ void __launch_bounds__(128) head_k(
    const float* __restrict__ Pp, const float* __restrict__ w4,
    const float* __restrict__ ls, float* __restrict__ O)
{
    __shared__ float sp[DIM];
    int b = blockIdx.y, tid = threadIdx.x;
    float m = NEG_INF;
#pragma unroll
    for (int c = 0; c < 7; c++) m = fmaxf(m, Pp[(b * 7 + c) * DIM + tid]);
    sp[tid] = m;
    __syncthreads();
    int c = blockIdx.x * 128 + tid;
    if (c < NCLS) {
        const float4* W = (const float4*)w4;
        float acc = NEG_INF;
#pragma unroll 4
        for (int j = 0; j < DIM; j += 4) {
            float4 w = W[(j >> 2) * NCLS + c];
            acc = fmaxf(acc, sp[j + 0] + w.x);
            acc = fmaxf(acc, sp[j + 1] + w.y);
            acc = fmaxf(acc, sp[j + 2] + w.z);
            acc = fmaxf(acc, sp[j + 3] + w.w);
        }
        O[(long)b * NCLS + c] = acc * ls[0];
    }
}

// ---------------- launch ----------------
extern "C" void kernel_launch(void* const* d_in, const int* in_sizes, int n_in,
                              void* d_out, int out_size)
{
    (void)in_sizes; (void)n_in; (void)out_size;
    const float* x      = (const float*)d_in[0];
    const float* embedW = (const float*)d_in[1];
    const float* pos    = (const float*)d_in[2];
    const float* W[2][5];
    const float* tau[2];
    for (int l = 0; l < 2; l++) {
        int base = 3 + l * 6;
        for (int k = 0; k < 5; k++) W[l][k] = (const float*)d_in[base + k];
        tau[l] = (const float*)d_in[base + 5];
    }
    const float* headW  = (const float*)d_in[15];
    const float* lscale = (const float*)d_in[16];
    float* out = (float*)d_out;

    float *h, *xn, *q, *kt4, *v4, *ffh, *poolp;
    float *wte4, *wtq4, *wtk4, *wtv4, *wt14, *wt24, *wth4;
    cudaGetSymbolAddress((void**)&h,    g_h);
    cudaGetSymbolAddress((void**)&xn,   g_xn);
    cudaGetSymbolAddress((void**)&q,    g_q);
    cudaGetSymbolAddress((void**)&kt4,  g_kt4);
    cudaGetSymbolAddress((void**)&v4,   g_v4);
    cudaGetSymbolAddress((void**)&ffh,  g_ffh);
    cudaGetSymbolAddress((void**)&poolp,g_poolp);
    cudaGetSymbolAddress((void**)&wte4, g_wte4);
    cudaGetSymbolAddress((void**)&wtq4, g_wtq4);
    cudaGetSymbolAddress((void**)&wtk4, g_wtk4);
    cudaGetSymbolAddress((void**)&wtv4, g_wtv4);
    cudaGetSymbolAddress((void**)&wt14, g_wt14);
    cudaGetSymbolAddress((void**)&wt24, g_wt24);
    cudaGetSymbolAddress((void**)&wth4, g_wth4);

    TJobs jobs;
    int base = 0, nj = 0;
    auto addJob = [&](const float* s, float* d, int I, int J) {
        jobs.j[nj].src = s; jobs.j[nj].dst = d; jobs.j[nj].I = I; jobs.j[nj].J = J;
        jobs.j[nj].base = base;
        base += ((J + 31) / 32) * ((I + 31) / 32);
        nj++;
    };
    addJob(embedW, wte4, DIM, PD);
    for (int l = 0; l < 2; l++) {
        addJob(W[l][0], wtq4 + l * DIM * DIM, DIM, DIM);
        addJob(W[l][1], wtk4 + l * DIM * DIM, DIM, DIM);
        addJob(W[l][2], wtv4 + l * DIM * DIM, DIM, DIM);
        addJob(W[l][3], wt14 + l * DFF * DIM, DFF, DIM);
        addJob(W[l][4], wt24 + l * DIM * DFF, DIM, DFF);
    }
    addJob(headW, wth4, NCLS, DIM);

    prep_k<<<base, 256>>>(jobs);
    embed_k<<<392, 128>>>(x, wte4, pos, h, xn);

    for (int l = 0; l < 2; l++) {
        qkv_k<<<dim3(392, 3), 128>>>(xn, wtq4 + l * DIM * DIM, wtk4 + l * DIM * DIM,
                                     wtv4 + l * DIM * DIM, q, kt4, v4);
        sa_k<<<dim3(49, 8), 256>>>(q, kt4, v4, h, xn);
        ff1_k<<<dim3(392, 2), 128>>>(xn, wt14 + l * DFF * DIM, tau[l], ffh);
        ff2_k<<<392, 128>>>(ffh, wt24 + l * DIM * DFF, h, xn);
    }

    pool1_k<<<dim3(8, 7), 128>>>(h, poolp);
    head_k<<<dim3(8, 8), 128>>>(poolp, wth4, lscale, out);
}